// round 5
// baseline (speedup 1.0000x reference)
#include <cuda_runtime.h>
#include <cstdint>

// Problem constants
#define Bsz 4
#define Ssz 2048
#define Hn  16
#define DKk 64
#define Dm  1024
#define Mrows (Bsz*Ssz)   // 8192

// ---------------- scratch (__device__ globals) ------------------------------
__device__ __align__(1024) float g_Q[(size_t)Bsz*Hn*Ssz*DKk];     // [B,H,S,dk] tf32-rounded
__device__ __align__(1024) float g_K[(size_t)Bsz*Hn*Ssz*DKk];
__device__ __align__(1024) float g_V[(size_t)Bsz*Hn*Ssz*DKk];
__device__ __align__(1024) float g_attn[(size_t)Mrows*Dm];        // [B*S, D] tf32-rounded
__device__ __align__(1024) float g_Xq[(size_t)Mrows*Dm];
__device__ __align__(1024) float g_Xk[(size_t)Mrows*Dm];
__device__ __align__(1024) float g_Xv[(size_t)Mrows*Dm];
__device__ __align__(1024) float g_Wq[(size_t)Dm*Dm];
__device__ __align__(1024) float g_Wk[(size_t)Dm*Dm];
__device__ __align__(1024) float g_Wv[(size_t)Dm*Dm];
__device__ __align__(1024) float g_Wo[(size_t)Dm*Dm];

// ---------------- helpers ----------------------------------------------------
__device__ __forceinline__ uint32_t smem_u32(const void* p) {
    uint32_t a;
    asm("{ .reg .u64 t; cvta.to.shared.u64 t, %1; cvt.u32.u64 %0, t; }" : "=r"(a) : "l"(p));
    return a;
}
__device__ __forceinline__ void cp_async16(uint32_t dst, const void* src) {
    asm volatile("cp.async.cg.shared.global [%0], [%1], 16;" :: "r"(dst), "l"(src));
}
#define CP_COMMIT() asm volatile("cp.async.commit_group;" ::: "memory")
#define CP_WAIT0()  asm volatile("cp.async.wait_group 0;" ::: "memory")
#define CP_WAIT1()  asm volatile("cp.async.wait_group 1;" ::: "memory")

__device__ __forceinline__ float tf32_rn(float x) {
    uint32_t u;
    asm("cvt.rna.tf32.f32 %0, %1;" : "=r"(u) : "f"(x));
    return __uint_as_float(u);
}
__device__ __forceinline__ void mma_tf32(float* c, const uint32_t* a, uint32_t b0, uint32_t b1) {
    asm volatile(
        "mma.sync.aligned.m16n8k8.row.col.f32.tf32.tf32.f32 "
        "{%0,%1,%2,%3}, {%4,%5,%6,%7}, {%8,%9}, {%0,%1,%2,%3};"
        : "+f"(c[0]), "+f"(c[1]), "+f"(c[2]), "+f"(c[3])
        : "r"(a[0]), "r"(a[1]), "r"(a[2]), "r"(a[3]), "r"(b0), "r"(b1));
}

// ---------------------------------------------------------------------------
// mma.sync tf32 NT GEMM, 3-stage cp.async pipeline.
// CTA 128x128x32, 8 warps (2x4), warp tile 64x32.
// ---------------------------------------------------------------------------
#define LDA 36
#define GEMM_SMEM_BYTES (6 * 4608 * 4)   // 110592 B (3 stages x (A+B))

__device__ __forceinline__ void gemm_mma_body(const float* __restrict__ X,
                                              const float* __restrict__ W,
                                              const float* __restrict__ bias,
                                              float* __restrict__ out,
                                              int layout)
{
    extern __shared__ float sm[];
    float* Abuf[3] = { sm,             sm + 4608,      sm + 2 * 4608 };
    float* Bbuf[3] = { sm + 3 * 4608,  sm + 4 * 4608,  sm + 5 * 4608 };

    const int tid  = threadIdx.x;
    const int lane = tid & 31, wid = tid >> 5;
    const int wm   = wid >> 2, wn = wid & 3;
    const int g    = lane >> 2, q = lane & 3;
    const int bm   = blockIdx.y * 128;
    const int bn   = blockIdx.x * 128;

    float acc[4][4][4];
#pragma unroll
    for (int i = 0; i < 4; i++)
#pragma unroll
        for (int j = 0; j < 4; j++)
#pragma unroll
            for (int k = 0; k < 4; k++) acc[i][j][k] = 0.f;

    auto issue_tile = [&](int kt, int buf) {
#pragma unroll
        for (int i = 0; i < 4; i++) {
            int idx = i * 256 + tid;
            int r = idx >> 3, c4 = idx & 7;
            cp_async16(smem_u32(&Abuf[buf][r * LDA + c4 * 4]),
                       X + (size_t)(bm + r) * Dm + kt * 32 + c4 * 4);
        }
#pragma unroll
        for (int i = 0; i < 4; i++) {
            int idx = i * 256 + tid;
            int r = idx >> 3, c4 = idx & 7;
            cp_async16(smem_u32(&Bbuf[buf][r * LDA + c4 * 4]),
                       W + (size_t)(bn + r) * Dm + kt * 32 + c4 * 4);
        }
        CP_COMMIT();
    };

    const int NT = Dm / 32;   // 32 k-tiles
    issue_tile(0, 0);
    issue_tile(1, 1);

    int buf = 0;
    for (int kt = 0; kt < NT; kt++) {
        if (kt + 1 < NT) { CP_WAIT1(); } else { CP_WAIT0(); }
        __syncthreads();
        if (kt + 2 < NT) {
            int nb = buf + 2; if (nb >= 3) nb -= 3;
            issue_tile(kt + 2, nb);
        }

        const float* Ab = Abuf[buf];
        const float* Bb = Bbuf[buf];
#pragma unroll
        for (int ks = 0; ks < 4; ks++) {
            uint32_t afr[4][4], bfr[4][2];
#pragma unroll
            for (int mt = 0; mt < 4; mt++) {
                const float* pa = Ab + (wm * 64 + mt * 16 + g) * LDA + ks * 8 + q;
                afr[mt][0] = __float_as_uint(pa[0]);
                afr[mt][1] = __float_as_uint(pa[8 * LDA]);
                afr[mt][2] = __float_as_uint(pa[4]);
                afr[mt][3] = __float_as_uint(pa[8 * LDA + 4]);
            }
#pragma unroll
            for (int nt = 0; nt < 4; nt++) {
                const float* pb = Bb + (wn * 32 + nt * 8 + g) * LDA + ks * 8 + q;
                bfr[nt][0] = __float_as_uint(pb[0]);
                bfr[nt][1] = __float_as_uint(pb[4]);
            }
#pragma unroll
            for (int mt = 0; mt < 4; mt++)
#pragma unroll
                for (int nt = 0; nt < 4; nt++)
                    mma_tf32(acc[mt][nt], afr[mt], bfr[nt][0], bfr[nt][1]);
        }
        __syncthreads();      // all readers done with 'buf' before its reuse
        buf = buf + 1; if (buf >= 3) buf = 0;
    }

#pragma unroll
    for (int mt = 0; mt < 4; mt++) {
        int r0 = bm + wm * 64 + mt * 16 + g;
#pragma unroll
        for (int nt = 0; nt < 4; nt++) {
            int n = bn + wn * 32 + nt * 8 + q * 2;
            float2 v0, v1;
            if (layout) {   // head-split output feeds tf32 attention: RN-round
                v0.x = tf32_rn(acc[mt][nt][0] + bias[n]);
                v0.y = tf32_rn(acc[mt][nt][1] + bias[n + 1]);
                v1.x = tf32_rn(acc[mt][nt][2] + bias[n]);
                v1.y = tf32_rn(acc[mt][nt][3] + bias[n + 1]);
                int h = n >> 6, d = n & 63;
                int b0i = r0 >> 11, s0 = r0 & (Ssz - 1);
                int r1 = r0 + 8;
                int b1i = r1 >> 11, s1 = r1 & (Ssz - 1);
                *(float2*)&out[((size_t)((b0i * Hn + h) * Ssz + s0)) * DKk + d] = v0;
                *(float2*)&out[((size_t)((b1i * Hn + h) * Ssz + s1)) * DKk + d] = v1;
            } else {
                v0.x = acc[mt][nt][0] + bias[n];
                v0.y = acc[mt][nt][1] + bias[n + 1];
                v1.x = acc[mt][nt][2] + bias[n];
                v1.y = acc[mt][nt][3] + bias[n + 1];
                *(float2*)&out[(size_t)r0 * Dm + n] = v0;
                *(float2*)&out[(size_t)(r0 + 8) * Dm + n] = v1;
            }
        }
    }
}

__global__ __launch_bounds__(256, 2) void gemm_qkv_tc(const float* __restrict__ bq,
                                                      const float* __restrict__ bk,
                                                      const float* __restrict__ bv)
{
    const float* X; const float* W; const float* bias; float* out;
    if (blockIdx.z == 0)      { X = g_Xq; W = g_Wq; bias = bq; out = g_Q; }
    else if (blockIdx.z == 1) { X = g_Xk; W = g_Wk; bias = bk; out = g_K; }
    else                      { X = g_Xv; W = g_Wv; bias = bv; out = g_V; }
    gemm_mma_body(X, W, bias, out, 1);
}

__global__ __launch_bounds__(256, 2) void gemm_out_tc(const float* __restrict__ bo,
                                                      float* __restrict__ out)
{
    gemm_mma_body(g_attn, g_Wo, bo, out, 0);
}

// ---------------------------------------------------------------------------
// tf32 RN pre-rounding of GEMM inputs
// ---------------------------------------------------------------------------
__global__ __launch_bounds__(256) void round_tf32_kern(const float* __restrict__ s,
                                                       float* __restrict__ d, int n4)
{
    int i = blockIdx.x * blockDim.x + threadIdx.x;
    if (i >= n4) return;
    float4 v = ((const float4*)s)[i];
    float4 o;
    o.x = tf32_rn(v.x); o.y = tf32_rn(v.y);
    o.z = tf32_rn(v.z); o.w = tf32_rn(v.w);
    ((float4*)d)[i] = o;
}

// ---------------------------------------------------------------------------
// Flash attention with mma.sync tf32. No V transpose: PV B-fragments load
// straight from the untransposed V tile (Vt[d][key] == Vs[key][d]).
// K and V double-buffered via cp.async (prefetch distance 1).
// CTA = 64 q-rows x bh, 4 warps, warp owns 16 rows.
// ---------------------------------------------------------------------------
#define LDK 68
#define TILE_F (64 * LDK)
#define ATT_SMEM (5 * TILE_F * 4)   // K x2, V x2, Ps = 87040 B

__global__ __launch_bounds__(128, 2) void attn_mma_kernel()
{
    extern __shared__ float smf[];
    float* Kbuf[2] = { smf,              smf + TILE_F };
    float* Vbuf[2] = { smf + 2 * TILE_F, smf + 3 * TILE_F };
    float* Ps      =   smf + 4 * TILE_F;   // [64][LDK] probs (per-warp rows)

    const int bh = blockIdx.y;
    const int qb = blockIdx.x * 64;
    const int tid = threadIdx.x;
    const int lane = tid & 31, w = tid >> 5;
    const int g = lane >> 2, q = lane & 3;

    const float* Qb = g_Q + (size_t)bh * Ssz * DKk;
    const float* Kb = g_K + (size_t)bh * Ssz * DKk;
    const float* Vb = g_V + (size_t)bh * Ssz * DKk;

    // ---- stage Q tile (scaled by 1/8, exact) into Ps area, grab fragments --
#pragma unroll
    for (int i = 0; i < 8; i++) {
        int idx = i * 128 + tid;
        int r = idx >> 4, c = (idx & 15) * 4;
        float4 v = *(const float4*)&Qb[(size_t)(qb + r) * DKk + c];
        v.x *= 0.125f; v.y *= 0.125f; v.z *= 0.125f; v.w *= 0.125f;
        *(float4*)&Ps[r * LDK + c] = v;
    }
    __syncthreads();

    uint32_t qfr[8][4];
#pragma unroll
    for (int ks = 0; ks < 8; ks++) {
        const float* pa = &Ps[(w * 16 + g) * LDK + ks * 8 + q];
        qfr[ks][0] = __float_as_uint(pa[0]);
        qfr[ks][1] = __float_as_uint(pa[8 * LDK]);
        qfr[ks][2] = __float_as_uint(pa[4]);
        qfr[ks][3] = __float_as_uint(pa[8 * LDK + 4]);
    }
    __syncthreads();   // Ps free for reuse

    auto issue_kv = [&](int kt, int bufi) {
        const float* Kp = Kb + (size_t)(kt * 64) * DKk;
        const float* Vp = Vb + (size_t)(kt * 64) * DKk;
        float* kd = Kbuf[bufi];
        float* vd = Vbuf[bufi];
#pragma unroll
        for (int i = 0; i < 8; i++) {
            int idx = i * 128 + tid;
            int r = idx >> 4, c = (idx & 15) * 4;
            cp_async16(smem_u32(&kd[r * LDK + c]), &Kp[r * DKk + c]);
            cp_async16(smem_u32(&vd[r * LDK + c]), &Vp[r * DKk + c]);
        }
        CP_COMMIT();
    };

    float oacc[8][4];
#pragma unroll
    for (int nt = 0; nt < 8; nt++)
#pragma unroll
        for (int k = 0; k < 4; k++) oacc[nt][k] = 0.f;
    float mA = -1e30f, mB = -1e30f, lA = 0.f, lB = 0.f;

    const int NT = Ssz / 64;   // 32 tiles
    issue_kv(0, 0);

    for (int kt = 0; kt < NT; kt++) {
        const int buf = kt & 1;
        if (kt + 1 < NT) {
            issue_kv(kt + 1, buf ^ 1);
            CP_WAIT1();
        } else {
            CP_WAIT0();
        }
        __syncthreads();

        const float* Ks = Kbuf[buf];
        const float* Vs = Vbuf[buf];

        // ---- S = Q * K^T : warp computes 16 x 64 ----
        float sacc[8][4];
#pragma unroll
        for (int nt = 0; nt < 8; nt++)
#pragma unroll
            for (int k = 0; k < 4; k++) sacc[nt][k] = 0.f;
#pragma unroll
        for (int nt = 0; nt < 8; nt++) {
#pragma unroll
            for (int ks = 0; ks < 8; ks++) {
                const float* pb = &Ks[(nt * 8 + g) * LDK + ks * 8 + q];
                mma_tf32(sacc[nt], qfr[ks],
                         __float_as_uint(pb[0]), __float_as_uint(pb[4]));
            }
        }

        // ---- online softmax (rows g and g+8 per thread) ----
        float mtA = -1e30f, mtB = -1e30f;
#pragma unroll
        for (int nt = 0; nt < 8; nt++) {
            mtA = fmaxf(mtA, fmaxf(sacc[nt][0], sacc[nt][1]));
            mtB = fmaxf(mtB, fmaxf(sacc[nt][2], sacc[nt][3]));
        }
        mtA = fmaxf(mtA, __shfl_xor_sync(0xffffffffu, mtA, 1));
        mtA = fmaxf(mtA, __shfl_xor_sync(0xffffffffu, mtA, 2));
        mtB = fmaxf(mtB, __shfl_xor_sync(0xffffffffu, mtB, 1));
        mtB = fmaxf(mtB, __shfl_xor_sync(0xffffffffu, mtB, 2));

        float mnA = fmaxf(mA, mtA), mnB = fmaxf(mB, mtB);
        float corrA = __expf(mA - mnA), corrB = __expf(mB - mnB);
        mA = mnA; mB = mnB;

        float sA = 0.f, sB = 0.f;
        float* prowA = &Ps[(w * 16 + g) * LDK];
        float* prowB = &Ps[(w * 16 + g + 8) * LDK];
#pragma unroll
        for (int nt = 0; nt < 8; nt++) {
            float p0 = __expf(sacc[nt][0] - mA);
            float p1 = __expf(sacc[nt][1] - mA);
            float p2 = __expf(sacc[nt][2] - mB);
            float p3 = __expf(sacc[nt][3] - mB);
            sA += p0 + p1;
            sB += p2 + p3;
            float2 vA = { tf32_rn(p0), tf32_rn(p1) };
            float2 vB = { tf32_rn(p2), tf32_rn(p3) };
            *(float2*)&prowA[nt * 8 + q * 2] = vA;
            *(float2*)&prowB[nt * 8 + q * 2] = vB;
        }
        sA += __shfl_xor_sync(0xffffffffu, sA, 1);
        sA += __shfl_xor_sync(0xffffffffu, sA, 2);
        sB += __shfl_xor_sync(0xffffffffu, sB, 1);
        sB += __shfl_xor_sync(0xffffffffu, sB, 2);
        lA = lA * corrA + sA;
        lB = lB * corrB + sB;

#pragma unroll
        for (int nt = 0; nt < 8; nt++) {
            oacc[nt][0] *= corrA; oacc[nt][1] *= corrA;
            oacc[nt][2] *= corrB; oacc[nt][3] *= corrB;
        }
        __syncwarp();

        // ---- O += P * V  (B fragments straight from untransposed Vs) ----
#pragma unroll
        for (int ks = 0; ks < 8; ks++) {
            uint32_t afr[4];
            const float* pa = &Ps[(w * 16 + g) * LDK + ks * 8 + q];
            afr[0] = __float_as_uint(pa[0]);
            afr[1] = __float_as_uint(pa[8 * LDK]);
            afr[2] = __float_as_uint(pa[4]);
            afr[3] = __float_as_uint(pa[8 * LDK + 4]);
#pragma unroll
            for (int nt = 0; nt < 8; nt++) {
                // b0 = Vt[nt*8+g][ks*8+q]   = Vs[ks*8+q][nt*8+g]
                // b1 = Vt[nt*8+g][ks*8+q+4] = Vs[ks*8+q+4][nt*8+g]
                const float b0 = Vs[(ks * 8 + q) * LDK + nt * 8 + g];
                const float b1 = Vs[(ks * 8 + q + 4) * LDK + nt * 8 + g];
                mma_tf32(oacc[nt], afr,
                         __float_as_uint(b0), __float_as_uint(b1));
            }
        }
        __syncthreads();   // all readers done with buf before its reuse
    }

    // ---- epilogue: normalize, tf32-RN round, write to g_attn -------------
    float invA = 1.f / lA, invB = 1.f / lB;
    int b = bh >> 4, h = bh & 15;
    int row0 = qb + w * 16 + g;
    int row1 = row0 + 8;
#pragma unroll
    for (int nt = 0; nt < 8; nt++) {
        int col = h * DKk + nt * 8 + q * 2;
        float2 v0 = { tf32_rn(oacc[nt][0] * invA), tf32_rn(oacc[nt][1] * invA) };
        float2 v1 = { tf32_rn(oacc[nt][2] * invB), tf32_rn(oacc[nt][3] * invB) };
        *(float2*)&g_attn[(size_t)(b * Ssz + row0) * Dm + col] = v0;
        *(float2*)&g_attn[(size_t)(b * Ssz + row1) * Dm + col] = v1;
    }
}

// ---------------------------------------------------------------------------
extern "C" void kernel_launch(void* const* d_in, const int* in_sizes, int n_in,
                              void* d_out, int out_size)
{
    const float* query = (const float*)d_in[0];
    const float* key_  = (const float*)d_in[1];
    const float* value = (const float*)d_in[2];
    const float* w_q   = (const float*)d_in[3];
    const float* b_q   = (const float*)d_in[4];
    const float* w_k   = (const float*)d_in[5];
    const float* b_k   = (const float*)d_in[6];
    const float* w_v   = (const float*)d_in[7];
    const float* b_v   = (const float*)d_in[8];
    const float* w_o   = (const float*)d_in[9];
    const float* b_o   = (const float*)d_in[10];
    float* out = (float*)d_out;

    cudaFuncSetAttribute(gemm_qkv_tc, cudaFuncAttributeMaxDynamicSharedMemorySize, GEMM_SMEM_BYTES);
    cudaFuncSetAttribute(gemm_out_tc, cudaFuncAttributeMaxDynamicSharedMemorySize, GEMM_SMEM_BYTES);
    cudaFuncSetAttribute(attn_mma_kernel, cudaFuncAttributeMaxDynamicSharedMemorySize, ATT_SMEM);

    float *dXq, *dXk, *dXv, *dWq, *dWk, *dWv, *dWo;
    cudaGetSymbolAddress((void**)&dXq, g_Xq);
    cudaGetSymbolAddress((void**)&dXk, g_Xk);
    cudaGetSymbolAddress((void**)&dXv, g_Xv);
    cudaGetSymbolAddress((void**)&dWq, g_Wq);
    cudaGetSymbolAddress((void**)&dWk, g_Wk);
    cudaGetSymbolAddress((void**)&dWv, g_Wv);
    cudaGetSymbolAddress((void**)&dWo, g_Wo);

    const int nX4 = Mrows * Dm / 4;
    const int nW4 = Dm * Dm / 4;

    round_tf32_kern<<<(nX4 + 255) / 256, 256>>>(query, dXq, nX4);
    round_tf32_kern<<<(nX4 + 255) / 256, 256>>>(key_,  dXk, nX4);
    round_tf32_kern<<<(nX4 + 255) / 256, 256>>>(value, dXv, nX4);
    round_tf32_kern<<<(nW4 + 255) / 256, 256>>>(w_q, dWq, nW4);
    round_tf32_kern<<<(nW4 + 255) / 256, 256>>>(w_k, dWk, nW4);
    round_tf32_kern<<<(nW4 + 255) / 256, 256>>>(w_v, dWv, nW4);
    round_tf32_kern<<<(nW4 + 255) / 256, 256>>>(w_o, dWo, nW4);

    gemm_qkv_tc<<<dim3(8, 64, 3), 256, GEMM_SMEM_BYTES>>>(b_q, b_k, b_v);

    attn_mma_kernel<<<dim3(32, 64), 128, ATT_SMEM>>>();

    gemm_out_tc<<<dim3(8, 64), 256, GEMM_SMEM_BYTES>>>(b_o, out);
}

// round 6
// speedup vs baseline: 1.1243x; 1.1243x over previous
#include <cuda_runtime.h>
#include <cstdint>

// Problem constants
#define Bsz 4
#define Ssz 2048
#define Hn  16
#define DKk 64
#define Dm  1024
#define Mrows (Bsz*Ssz)   // 8192

// ---------------- scratch (__device__ globals) ------------------------------
__device__ __align__(1024) float g_Q[(size_t)Bsz*Hn*Ssz*DKk];     // [B,H,S,dk] tf32-rounded
__device__ __align__(1024) float g_K[(size_t)Bsz*Hn*Ssz*DKk];
__device__ __align__(1024) float g_V[(size_t)Bsz*Hn*Ssz*DKk];
__device__ __align__(1024) float g_attn[(size_t)Mrows*Dm];        // [B*S, D] tf32-rounded
__device__ __align__(1024) float g_Xq[(size_t)Mrows*Dm];
__device__ __align__(1024) float g_Xk[(size_t)Mrows*Dm];
__device__ __align__(1024) float g_Xv[(size_t)Mrows*Dm];
__device__ __align__(1024) float g_Wq[(size_t)Dm*Dm];
__device__ __align__(1024) float g_Wk[(size_t)Dm*Dm];
__device__ __align__(1024) float g_Wv[(size_t)Dm*Dm];
__device__ __align__(1024) float g_Wo[(size_t)Dm*Dm];

// ---------------- helpers ----------------------------------------------------
__device__ __forceinline__ uint32_t smem_u32(const void* p) {
    uint32_t a;
    asm("{ .reg .u64 t; cvta.to.shared.u64 t, %1; cvt.u32.u64 %0, t; }" : "=r"(a) : "l"(p));
    return a;
}
__device__ __forceinline__ void cp_async16(uint32_t dst, const void* src) {
    asm volatile("cp.async.cg.shared.global [%0], [%1], 16;" :: "r"(dst), "l"(src));
}
#define CP_COMMIT() asm volatile("cp.async.commit_group;" ::: "memory")
#define CP_WAIT0()  asm volatile("cp.async.wait_group 0;" ::: "memory")
#define CP_WAIT1()  asm volatile("cp.async.wait_group 1;" ::: "memory")

__device__ __forceinline__ float tf32_rn(float x) {
    uint32_t u;
    asm("cvt.rna.tf32.f32 %0, %1;" : "=r"(u) : "f"(x));
    return __uint_as_float(u);
}
__device__ __forceinline__ void mma_tf32(float* c, const uint32_t* a, uint32_t b0, uint32_t b1) {
    asm volatile(
        "mma.sync.aligned.m16n8k8.row.col.f32.tf32.tf32.f32 "
        "{%0,%1,%2,%3}, {%4,%5,%6,%7}, {%8,%9}, {%0,%1,%2,%3};"
        : "+f"(c[0]), "+f"(c[1]), "+f"(c[2]), "+f"(c[3])
        : "r"(a[0]), "r"(a[1]), "r"(a[2]), "r"(a[3]), "r"(b0), "r"(b1));
}

// ---------------------------------------------------------------------------
// mma.sync tf32 NT GEMM, 3-stage cp.async pipeline (unchanged from R5).
// ---------------------------------------------------------------------------
#define LDA 36
#define GEMM_SMEM_BYTES (6 * 4608 * 4)

__device__ __forceinline__ void gemm_mma_body(const float* __restrict__ X,
                                              const float* __restrict__ W,
                                              const float* __restrict__ bias,
                                              float* __restrict__ out,
                                              int layout)
{
    extern __shared__ float sm[];
    float* Abuf[3] = { sm,             sm + 4608,      sm + 2 * 4608 };
    float* Bbuf[3] = { sm + 3 * 4608,  sm + 4 * 4608,  sm + 5 * 4608 };

    const int tid  = threadIdx.x;
    const int lane = tid & 31, wid = tid >> 5;
    const int wm   = wid >> 2, wn = wid & 3;
    const int g    = lane >> 2, q = lane & 3;
    const int bm   = blockIdx.y * 128;
    const int bn   = blockIdx.x * 128;

    float acc[4][4][4];
#pragma unroll
    for (int i = 0; i < 4; i++)
#pragma unroll
        for (int j = 0; j < 4; j++)
#pragma unroll
            for (int k = 0; k < 4; k++) acc[i][j][k] = 0.f;

    auto issue_tile = [&](int kt, int buf) {
#pragma unroll
        for (int i = 0; i < 4; i++) {
            int idx = i * 256 + tid;
            int r = idx >> 3, c4 = idx & 7;
            cp_async16(smem_u32(&Abuf[buf][r * LDA + c4 * 4]),
                       X + (size_t)(bm + r) * Dm + kt * 32 + c4 * 4);
        }
#pragma unroll
        for (int i = 0; i < 4; i++) {
            int idx = i * 256 + tid;
            int r = idx >> 3, c4 = idx & 7;
            cp_async16(smem_u32(&Bbuf[buf][r * LDA + c4 * 4]),
                       W + (size_t)(bn + r) * Dm + kt * 32 + c4 * 4);
        }
        CP_COMMIT();
    };

    const int NT = Dm / 32;
    issue_tile(0, 0);
    issue_tile(1, 1);

    int buf = 0;
    for (int kt = 0; kt < NT; kt++) {
        if (kt + 1 < NT) { CP_WAIT1(); } else { CP_WAIT0(); }
        __syncthreads();
        if (kt + 2 < NT) {
            int nb = buf + 2; if (nb >= 3) nb -= 3;
            issue_tile(kt + 2, nb);
        }

        const float* Ab = Abuf[buf];
        const float* Bb = Bbuf[buf];
#pragma unroll
        for (int ks = 0; ks < 4; ks++) {
            uint32_t afr[4][4], bfr[4][2];
#pragma unroll
            for (int mt = 0; mt < 4; mt++) {
                const float* pa = Ab + (wm * 64 + mt * 16 + g) * LDA + ks * 8 + q;
                afr[mt][0] = __float_as_uint(pa[0]);
                afr[mt][1] = __float_as_uint(pa[8 * LDA]);
                afr[mt][2] = __float_as_uint(pa[4]);
                afr[mt][3] = __float_as_uint(pa[8 * LDA + 4]);
            }
#pragma unroll
            for (int nt = 0; nt < 4; nt++) {
                const float* pb = Bb + (wn * 32 + nt * 8 + g) * LDA + ks * 8 + q;
                bfr[nt][0] = __float_as_uint(pb[0]);
                bfr[nt][1] = __float_as_uint(pb[4]);
            }
#pragma unroll
            for (int mt = 0; mt < 4; mt++)
#pragma unroll
                for (int nt = 0; nt < 4; nt++)
                    mma_tf32(acc[mt][nt], afr[mt], bfr[nt][0], bfr[nt][1]);
        }
        __syncthreads();
        buf = buf + 1; if (buf >= 3) buf = 0;
    }

#pragma unroll
    for (int mt = 0; mt < 4; mt++) {
        int r0 = bm + wm * 64 + mt * 16 + g;
#pragma unroll
        for (int nt = 0; nt < 4; nt++) {
            int n = bn + wn * 32 + nt * 8 + q * 2;
            float2 v0, v1;
            if (layout) {
                v0.x = tf32_rn(acc[mt][nt][0] + bias[n]);
                v0.y = tf32_rn(acc[mt][nt][1] + bias[n + 1]);
                v1.x = tf32_rn(acc[mt][nt][2] + bias[n]);
                v1.y = tf32_rn(acc[mt][nt][3] + bias[n + 1]);
                int h = n >> 6, d = n & 63;
                int b0i = r0 >> 11, s0 = r0 & (Ssz - 1);
                int r1 = r0 + 8;
                int b1i = r1 >> 11, s1 = r1 & (Ssz - 1);
                *(float2*)&out[((size_t)((b0i * Hn + h) * Ssz + s0)) * DKk + d] = v0;
                *(float2*)&out[((size_t)((b1i * Hn + h) * Ssz + s1)) * DKk + d] = v1;
            } else {
                v0.x = acc[mt][nt][0] + bias[n];
                v0.y = acc[mt][nt][1] + bias[n + 1];
                v1.x = acc[mt][nt][2] + bias[n];
                v1.y = acc[mt][nt][3] + bias[n + 1];
                *(float2*)&out[(size_t)r0 * Dm + n] = v0;
                *(float2*)&out[(size_t)(r0 + 8) * Dm + n] = v1;
            }
        }
    }
}

__global__ __launch_bounds__(256, 2) void gemm_qkv_tc(const float* __restrict__ bq,
                                                      const float* __restrict__ bk,
                                                      const float* __restrict__ bv)
{
    const float* X; const float* W; const float* bias; float* out;
    if (blockIdx.z == 0)      { X = g_Xq; W = g_Wq; bias = bq; out = g_Q; }
    else if (blockIdx.z == 1) { X = g_Xk; W = g_Wk; bias = bk; out = g_K; }
    else                      { X = g_Xv; W = g_Wv; bias = bv; out = g_V; }
    gemm_mma_body(X, W, bias, out, 1);
}

__global__ __launch_bounds__(256, 2) void gemm_out_tc(const float* __restrict__ bo,
                                                      float* __restrict__ out)
{
    gemm_mma_body(g_attn, g_Wo, bo, out, 0);
}

// ---------------------------------------------------------------------------
// Fused tf32 RN pre-rounding: one launch for X (q,k,v), one for W (q,k,v,o)
// ---------------------------------------------------------------------------
__global__ __launch_bounds__(256) void round_x3(const float* __restrict__ xq,
                                                const float* __restrict__ xk,
                                                const float* __restrict__ xv)
{
    const float* s; float* d;
    if (blockIdx.z == 0)      { s = xq; d = g_Xq; }
    else if (blockIdx.z == 1) { s = xk; d = g_Xk; }
    else                      { s = xv; d = g_Xv; }
    int i = blockIdx.x * blockDim.x + threadIdx.x;
    float4 v = ((const float4*)s)[i];
    float4 o;
    o.x = tf32_rn(v.x); o.y = tf32_rn(v.y);
    o.z = tf32_rn(v.z); o.w = tf32_rn(v.w);
    ((float4*)d)[i] = o;
}

__global__ __launch_bounds__(256) void round_w4(const float* __restrict__ wq,
                                                const float* __restrict__ wk,
                                                const float* __restrict__ wv,
                                                const float* __restrict__ wo)
{
    const float* s; float* d;
    if (blockIdx.z == 0)      { s = wq; d = g_Wq; }
    else if (blockIdx.z == 1) { s = wk; d = g_Wk; }
    else if (blockIdx.z == 2) { s = wv; d = g_Wv; }
    else                      { s = wo; d = g_Wo; }
    int i = blockIdx.x * blockDim.x + threadIdx.x;
    float4 v = ((const float4*)s)[i];
    float4 o;
    o.x = tf32_rn(v.x); o.y = tf32_rn(v.y);
    o.z = tf32_rn(v.z); o.w = tf32_rn(v.w);
    ((float4*)d)[i] = o;
}

// ---------------------------------------------------------------------------
// Flash attention, mma.sync tf32.
// CTA = 128 q-rows x bh, 4 warps, warp owns 32 rows (2 m-tiles of 16).
// PV B-fragments (V) reused across both m-tiles -> fewer LDS per MMA.
// K/V double-buffered cp.async. Halved grid halves K/V L2 traffic.
// ---------------------------------------------------------------------------
#define LDK 68
#define TILE_F (64 * LDK)
#define ATT_SMEM ((4 * TILE_F + 128 * LDK) * 4)   // K x2, V x2, Ps[128] = 104448 B

__global__ __launch_bounds__(128, 2) void attn_mma_kernel()
{
    extern __shared__ float smf[];
    float* Kbuf[2] = { smf,              smf + TILE_F };
    float* Vbuf[2] = { smf + 2 * TILE_F, smf + 3 * TILE_F };
    float* Ps      =   smf + 4 * TILE_F;   // [128][LDK]

    const int bh = blockIdx.y;
    const int qb = blockIdx.x * 128;
    const int tid = threadIdx.x;
    const int lane = tid & 31, w = tid >> 5;
    const int g = lane >> 2, q = lane & 3;

    const float* Qb = g_Q + (size_t)bh * Ssz * DKk;
    const float* Kb = g_K + (size_t)bh * Ssz * DKk;
    const float* Vb = g_V + (size_t)bh * Ssz * DKk;

    // ---- stage Q tile (128 rows, scaled 1/8) into Ps, grab fragments ------
#pragma unroll
    for (int i = 0; i < 16; i++) {
        int idx = i * 128 + tid;
        int r = idx >> 4, c = (idx & 15) * 4;
        float4 v = *(const float4*)&Qb[(size_t)(qb + r) * DKk + c];
        v.x *= 0.125f; v.y *= 0.125f; v.z *= 0.125f; v.w *= 0.125f;
        *(float4*)&Ps[r * LDK + c] = v;
    }
    __syncthreads();

    uint32_t qfr[2][8][4];
#pragma unroll
    for (int mt = 0; mt < 2; mt++)
#pragma unroll
        for (int ks = 0; ks < 8; ks++) {
            const float* pa = &Ps[(w * 32 + mt * 16 + g) * LDK + ks * 8 + q];
            qfr[mt][ks][0] = __float_as_uint(pa[0]);
            qfr[mt][ks][1] = __float_as_uint(pa[8 * LDK]);
            qfr[mt][ks][2] = __float_as_uint(pa[4]);
            qfr[mt][ks][3] = __float_as_uint(pa[8 * LDK + 4]);
        }
    __syncthreads();   // Ps free for reuse

    auto issue_kv = [&](int kt, int bufi) {
        const float* Kp = Kb + (size_t)(kt * 64) * DKk;
        const float* Vp = Vb + (size_t)(kt * 64) * DKk;
        float* kd = Kbuf[bufi];
        float* vd = Vbuf[bufi];
#pragma unroll
        for (int i = 0; i < 8; i++) {
            int idx = i * 128 + tid;
            int r = idx >> 4, c = (idx & 15) * 4;
            cp_async16(smem_u32(&kd[r * LDK + c]), &Kp[r * DKk + c]);
            cp_async16(smem_u32(&vd[r * LDK + c]), &Vp[r * DKk + c]);
        }
        CP_COMMIT();
    };

    float oacc[2][8][4];
#pragma unroll
    for (int mt = 0; mt < 2; mt++)
#pragma unroll
        for (int nt = 0; nt < 8; nt++)
#pragma unroll
            for (int k = 0; k < 4; k++) oacc[mt][nt][k] = 0.f;
    float mr[2][2] = { {-1e30f, -1e30f}, {-1e30f, -1e30f} };   // [mt][A/B]
    float lr[2][2] = { {0.f, 0.f}, {0.f, 0.f} };

    const int NT = Ssz / 64;
    issue_kv(0, 0);

    for (int kt = 0; kt < NT; kt++) {
        const int buf = kt & 1;
        if (kt + 1 < NT) {
            issue_kv(kt + 1, buf ^ 1);
            CP_WAIT1();
        } else {
            CP_WAIT0();
        }
        __syncthreads();

        const float* Ks = Kbuf[buf];
        const float* Vs = Vbuf[buf];

        // ---- per m-tile: S = Q K^T, online softmax, P -> Ps ----
#pragma unroll
        for (int mt = 0; mt < 2; mt++) {
            float sacc[8][4];
#pragma unroll
            for (int nt = 0; nt < 8; nt++)
#pragma unroll
                for (int k = 0; k < 4; k++) sacc[nt][k] = 0.f;
#pragma unroll
            for (int nt = 0; nt < 8; nt++) {
#pragma unroll
                for (int ks = 0; ks < 8; ks++) {
                    const float* pb = &Ks[(nt * 8 + g) * LDK + ks * 8 + q];
                    mma_tf32(sacc[nt], qfr[mt][ks],
                             __float_as_uint(pb[0]), __float_as_uint(pb[4]));
                }
            }

            float mtA = -1e30f, mtB = -1e30f;
#pragma unroll
            for (int nt = 0; nt < 8; nt++) {
                mtA = fmaxf(mtA, fmaxf(sacc[nt][0], sacc[nt][1]));
                mtB = fmaxf(mtB, fmaxf(sacc[nt][2], sacc[nt][3]));
            }
            mtA = fmaxf(mtA, __shfl_xor_sync(0xffffffffu, mtA, 1));
            mtA = fmaxf(mtA, __shfl_xor_sync(0xffffffffu, mtA, 2));
            mtB = fmaxf(mtB, __shfl_xor_sync(0xffffffffu, mtB, 1));
            mtB = fmaxf(mtB, __shfl_xor_sync(0xffffffffu, mtB, 2));

            float mnA = fmaxf(mr[mt][0], mtA), mnB = fmaxf(mr[mt][1], mtB);
            float corrA = __expf(mr[mt][0] - mnA), corrB = __expf(mr[mt][1] - mnB);
            mr[mt][0] = mnA; mr[mt][1] = mnB;

            float sA = 0.f, sB = 0.f;
            float* prowA = &Ps[(w * 32 + mt * 16 + g) * LDK];
            float* prowB = &Ps[(w * 32 + mt * 16 + g + 8) * LDK];
#pragma unroll
            for (int nt = 0; nt < 8; nt++) {
                float p0 = __expf(sacc[nt][0] - mnA);
                float p1 = __expf(sacc[nt][1] - mnA);
                float p2 = __expf(sacc[nt][2] - mnB);
                float p3 = __expf(sacc[nt][3] - mnB);
                sA += p0 + p1;
                sB += p2 + p3;
                float2 vA = { tf32_rn(p0), tf32_rn(p1) };
                float2 vB = { tf32_rn(p2), tf32_rn(p3) };
                *(float2*)&prowA[nt * 8 + q * 2] = vA;
                *(float2*)&prowB[nt * 8 + q * 2] = vB;
            }
            sA += __shfl_xor_sync(0xffffffffu, sA, 1);
            sA += __shfl_xor_sync(0xffffffffu, sA, 2);
            sB += __shfl_xor_sync(0xffffffffu, sB, 1);
            sB += __shfl_xor_sync(0xffffffffu, sB, 2);
            lr[mt][0] = lr[mt][0] * corrA + sA;
            lr[mt][1] = lr[mt][1] * corrB + sB;

#pragma unroll
            for (int nt = 0; nt < 8; nt++) {
                oacc[mt][nt][0] *= corrA; oacc[mt][nt][1] *= corrA;
                oacc[mt][nt][2] *= corrB; oacc[mt][nt][3] *= corrB;
            }
        }
        __syncwarp();

        // ---- O += P * V : V fragments shared across both m-tiles ----
#pragma unroll
        for (int ks = 0; ks < 8; ks++) {
            uint32_t afr[2][4];
#pragma unroll
            for (int mt = 0; mt < 2; mt++) {
                const float* pa = &Ps[(w * 32 + mt * 16 + g) * LDK + ks * 8 + q];
                afr[mt][0] = __float_as_uint(pa[0]);
                afr[mt][1] = __float_as_uint(pa[8 * LDK]);
                afr[mt][2] = __float_as_uint(pa[4]);
                afr[mt][3] = __float_as_uint(pa[8 * LDK + 4]);
            }
#pragma unroll
            for (int nt = 0; nt < 8; nt++) {
                const uint32_t b0 = __float_as_uint(Vs[(ks * 8 + q) * LDK + nt * 8 + g]);
                const uint32_t b1 = __float_as_uint(Vs[(ks * 8 + q + 4) * LDK + nt * 8 + g]);
                mma_tf32(oacc[0][nt], afr[0], b0, b1);
                mma_tf32(oacc[1][nt], afr[1], b0, b1);
            }
        }
        __syncthreads();
    }

    // ---- epilogue ----------------------------------------------------------
    int b = bh >> 4, h = bh & 15;
#pragma unroll
    for (int mt = 0; mt < 2; mt++) {
        float invA = 1.f / lr[mt][0], invB = 1.f / lr[mt][1];
        int row0 = qb + w * 32 + mt * 16 + g;
        int row1 = row0 + 8;
#pragma unroll
        for (int nt = 0; nt < 8; nt++) {
            int col = h * DKk + nt * 8 + q * 2;
            float2 v0 = { tf32_rn(oacc[mt][nt][0] * invA), tf32_rn(oacc[mt][nt][1] * invA) };
            float2 v1 = { tf32_rn(oacc[mt][nt][2] * invB), tf32_rn(oacc[mt][nt][3] * invB) };
            *(float2*)&g_attn[(size_t)(b * Ssz + row0) * Dm + col] = v0;
            *(float2*)&g_attn[(size_t)(b * Ssz + row1) * Dm + col] = v1;
        }
    }
}

// ---------------------------------------------------------------------------
extern "C" void kernel_launch(void* const* d_in, const int* in_sizes, int n_in,
                              void* d_out, int out_size)
{
    const float* query = (const float*)d_in[0];
    const float* key_  = (const float*)d_in[1];
    const float* value = (const float*)d_in[2];
    const float* w_q   = (const float*)d_in[3];
    const float* b_q   = (const float*)d_in[4];
    const float* w_k   = (const float*)d_in[5];
    const float* b_k   = (const float*)d_in[6];
    const float* w_v   = (const float*)d_in[7];
    const float* b_v   = (const float*)d_in[8];
    const float* w_o   = (const float*)d_in[9];
    const float* b_o   = (const float*)d_in[10];
    float* out = (float*)d_out;

    cudaFuncSetAttribute(gemm_qkv_tc, cudaFuncAttributeMaxDynamicSharedMemorySize, GEMM_SMEM_BYTES);
    cudaFuncSetAttribute(gemm_out_tc, cudaFuncAttributeMaxDynamicSharedMemorySize, GEMM_SMEM_BYTES);
    cudaFuncSetAttribute(attn_mma_kernel, cudaFuncAttributeMaxDynamicSharedMemorySize, ATT_SMEM);

    const int nX4 = Mrows * Dm / 4;   // 2,097,152
    const int nW4 = Dm * Dm / 4;      //   262,144

    // 1) tf32 RN pre-rounding (2 fused launches)
    round_x3<<<dim3(nX4 / 256, 1, 3), 256>>>(query, key_, value);
    round_w4<<<dim3(nW4 / 256, 1, 4), 256>>>(w_q, w_k, w_v, w_o);

    // 2) QKV projections (mma.sync tf32) into head-split scratch
    gemm_qkv_tc<<<dim3(8, 64, 3), 256, GEMM_SMEM_BYTES>>>(b_q, b_k, b_v);

    // 3) attention (mma.sync tf32 flash), 128-row q-tiles
    attn_mma_kernel<<<dim3(16, 64), 128, ATT_SMEM>>>();

    // 4) output projection -> d_out
    gemm_out_tc<<<dim3(8, 64), 256, GEMM_SMEM_BYTES>>>(b_o, out);
}